// round 10
// baseline (speedup 1.0000x reference)
#include <cuda_runtime.h>

#define BB 128
#define HH 256
#define WW 256
#define SHIFT 32
#define HW (HH*WW)      // 65536
#define CHW (3*HW)      // 196608
#define HW4 (HW/4)      // 16384 float4 per plane
#define RBLKS 16        // reduce role-units per image
#define BPI 64          // transform role-units per image
#define Q0 32           // images reduced in K0 / transformed in K1
#define Q123 (BB - Q0)  // 96 images reduced in K1 / transformed in K2

__device__ float g_part[BB * RBLKS];

// ---- reduce role: one block sums 1/16 of one image, writes one partial ----
__device__ __forceinline__ void reduce_role(const float* __restrict__ imgs,
                                            int b, int blk)
{
    const float4* p = (const float4*)(imgs + (size_t)b * CHW)
                    + blk * ((CHW / 4) / RBLKS) + threadIdx.x;
    float4 v[12];
    #pragma unroll
    for (int i = 0; i < 12; i++) v[i] = p[i * 256];
    float s0 = 0.f, s1 = 0.f, s2 = 0.f, s3 = 0.f;
    #pragma unroll
    for (int i = 0; i < 12; i += 4) {
        s0 += (v[i].x   + v[i].y)   + (v[i].z   + v[i].w);
        s1 += (v[i+1].x + v[i+1].y) + (v[i+1].z + v[i+1].w);
        s2 += (v[i+2].x + v[i+2].y) + (v[i+2].z + v[i+2].w);
        s3 += (v[i+3].x + v[i+3].y) + (v[i+3].z + v[i+3].w);
    }
    float s = (s0 + s1) + (s2 + s3);
    #pragma unroll
    for (int o = 16; o; o >>= 1) s += __shfl_down_sync(0xffffffffu, s, o);
    __shared__ float ss[8];
    if ((threadIdx.x & 31) == 0) ss[threadIdx.x >> 5] = s;
    __syncthreads();
    if (threadIdx.x < 8) {
        s = ss[threadIdx.x];
        #pragma unroll
        for (int o = 4; o; o >>= 1) s += __shfl_down_sync(0xffu, s, o);
        if (threadIdx.x == 0) g_part[b * RBLKS + blk] = s;
    }
}

// Select the 4 floats starting at component s of the concatenation [A|B].
// s is per-image uniform -> branch-uniform switch.
__device__ __forceinline__ float4 sel4(float4 A, float4 B, int s) {
    switch (s & 3) {
    case 0:  return A;
    case 1:  return make_float4(A.y, A.z, A.w, B.x);
    case 2:  return make_float4(A.z, A.w, B.x, B.y);
    default: return make_float4(A.w, B.x, B.y, B.z);
    }
}

// ---- transform role: one output float4 per thread in each of 3 planes.
// Gather reads are 2 aligned LDG.128 per plane (span of the shifted window),
// component-selected by the per-image shift remainder.
__device__ __forceinline__ void transform_role(
    const float* __restrict__ imgs,
    const float* __restrict__ br,  const float* __restrict__ sat,
    const float* __restrict__ con, const int* __restrict__ tx,
    const int* __restrict__ ty,    const int* __restrict__ cx,
    const int* __restrict__ cy,    float* __restrict__ out,
    int b, int blk)
{
    int idx4 = blk * 256 + threadIdx.x;               // float4 index in plane
    int h    = idx4 >> 6;
    int w0   = (idx4 & 63) << 2;

    // Half a warp sums this image's 16 partials (L2-broadcast hits).
    __shared__ float sM0;
    if (threadIdx.x < 16) {
        float s = g_part[b * RBLKS + threadIdx.x];
        #pragma unroll
        for (int o = 8; o; o >>= 1) s += __shfl_down_sync(0xffffu, s, o);
        if (threadIdx.x == 0) sM0 = s * (1.0f / (float)CHW);
    }
    __syncthreads();

    float a  = sat[b] * 2.0f;
    float k  = con[b] + 0.5f;
    float Af = k * a;
    float Bf = k * (1.0f - a);
    float Cf = (1.0f - k) * sM0 + (br[b] - 0.5f);

    int txs = tx[b] - SHIFT;
    int tys = ty[b] - SHIFT;
    int cxv = cx[b], cyv = cy[b];
    int xlo = max(0, cxv - 64), xhi = min(HH - 1, cxv + 63);
    int ylo = max(0, cyv - 64), yhi = min(WW - 1, cyv + 63);

    int  sh       = h + txs;
    bool rowvalid = (sh >= 0) & (sh < HH);
    bool rowcut   = (h >= xlo) & (h <= xhi);
    int  sh_c     = min(max(sh, 0), HH - 1);

    // Shifted window [sw0, sw0+3] lies in aligned float4s base, base+1.
    int sw0  = w0 + tys;
    int s    = sw0 & 3;
    int base = sw0 >> 2;                               // arithmetic shift: floor
    int bA   = min(max(base,     0), 63);
    int bB   = min(max(base + 1, 0), 63);

    const float4* srow = (const float4*)(imgs + (size_t)b * CHW) + (size_t)sh_c * 64;

    // Batch all 6 loads for MLP
    float4 A0 = __ldcs(srow + bA),            B0 = __ldcs(srow + bB);
    float4 A1 = __ldcs(srow + HW4 + bA),      B1 = __ldcs(srow + HW4 + bB);
    float4 A2 = __ldcs(srow + 2*HW4 + bA),    B2 = __ldcs(srow + 2*HW4 + bB);

    float4 v0 = sel4(A0, B0, s);
    float4 v1 = sel4(A1, B1, s);
    float4 v2 = sel4(A2, B2, s);

    float p0[4] = {v0.x, v0.y, v0.z, v0.w};
    float p1[4] = {v1.x, v1.y, v1.z, v1.w};
    float p2[4] = {v2.x, v2.y, v2.z, v2.w};

    float o0[4], o1[4], o2[4];
    #pragma unroll
    for (int j = 0; j < 4; j++) {
        int  w  = w0 + j;
        int  sw = sw0 + j;
        bool valid = rowvalid & (sw >= 0) & (sw < WW)
                   & !(rowcut & (w >= ylo) & (w <= yhi));
        float m  = (p0[j] + p1[j] + p2[j]) * (1.0f / 3.0f);
        float bm = fmaf(Bf, m, Cf);
        o0[j] = valid ? fmaf(Af, p0[j], bm) : 0.f;
        o1[j] = valid ? fmaf(Af, p1[j], bm) : 0.f;
        o2[j] = valid ? fmaf(Af, p2[j], bm) : 0.f;
    }

    float* dst = out + (size_t)b * CHW + (size_t)h * WW + w0;
    __stcs((float4*)(dst),          make_float4(o0[0], o0[1], o0[2], o0[3]));
    __stcs((float4*)(dst + HW),     make_float4(o1[0], o1[1], o1[2], o1[3]));
    __stcs((float4*)(dst + 2 * HW), make_float4(o2[0], o2[1], o2[2], o2[3]));
}

// Mixed kernel: FIRST nred*RBLKS blocks reduce images [rbase, rbase+nred)
// (dispatched earliest: their DRAM reads are the long pole and feed the next
// node). Remaining ntr*BPI blocks transform images [tbase, tbase+ntr), whose
// partials were completed by the PREVIOUS node (inter-node barrier orders it).
__global__ void __launch_bounds__(256) fused_kernel(
    const float* __restrict__ imgs,
    const float* __restrict__ br,  const float* __restrict__ sat,
    const float* __restrict__ con, const int* __restrict__ tx,
    const int* __restrict__ ty,    const int* __restrict__ cx,
    const int* __restrict__ cy,    float* __restrict__ out,
    int tbase, int rbase, int nred)
{
    int nredblk = nred * RBLKS;
    if ((int)blockIdx.x < nredblk) {
        reduce_role(imgs, rbase + blockIdx.x / RBLKS, blockIdx.x % RBLKS);
    } else {
        int tix = blockIdx.x - nredblk;
        transform_role(imgs, br, sat, con, tx, ty, cx, cy, out,
                       tbase + tix / BPI, tix % BPI);
    }
}

extern "C" void kernel_launch(void* const* d_in, const int* in_sizes, int n_in,
                              void* d_out, int out_size)
{
    const float* imgs = (const float*)d_in[0];
    const float* br   = (const float*)d_in[1];
    const float* sat  = (const float*)d_in[2];
    const float* con  = (const float*)d_in[3];
    const int*   tx   = (const int*)d_in[4];
    const int*   ty   = (const int*)d_in[5];
    const int*   cx   = (const int*)d_in[6];
    const int*   cy   = (const int*)d_in[7];
    float*       out  = (float*)d_out;

    // K0: reduce q0 only (small read-only endcap)
    fused_kernel<<<Q0 * RBLKS, 256>>>(imgs, br, sat, con, tx, ty, cx, cy, out,
                                      /*tbase*/0, /*rbase*/0, /*nred*/Q0);
    // K1: reduce q1..q3 (75MB read) + transform q0 (25MB write, L2-hot reads)
    fused_kernel<<<Q123 * RBLKS + Q0 * BPI, 256>>>(imgs, br, sat, con, tx, ty, cx, cy, out,
                                      /*tbase*/0, /*rbase*/Q0, /*nred*/Q123);
    // K2: transform q1..q3 (75MB write, reads L2-resident from K1)
    fused_kernel<<<Q123 * BPI, 256>>>(imgs, br, sat, con, tx, ty, cx, cy, out,
                                      /*tbase*/Q0, /*rbase*/0, /*nred*/0);
}

// round 11
// speedup vs baseline: 1.0948x; 1.0948x over previous
#include <cuda_runtime.h>

#define BB 128
#define HH 256
#define WW 256
#define SHIFT 32
#define HW (HH*WW)      // 65536
#define CHW (3*HW)      // 196608
#define RBLKS 32        // reduce role-units per image
#define BPI 64          // transform role-units per image
#define HALF (BB/2)     // 64 images per chunk

__device__ float g_part[BB * RBLKS];

// ---- reduce role: one block sums 1/32 of one image, writes one partial ----
__device__ __forceinline__ void reduce_role(const float* __restrict__ imgs,
                                            int b, int blk)
{
    const float4* p = (const float4*)(imgs + (size_t)b * CHW);
    const int per_blk = (CHW / 4) / RBLKS;   // 1536 float4
    int base = blk * per_blk;
    float s0 = 0.f, s1 = 0.f;
    #pragma unroll
    for (int i = 0; i < 6; i += 2) {         // front-batched
        float4 va = p[base + i * 256 + threadIdx.x];
        float4 vb = p[base + (i + 1) * 256 + threadIdx.x];
        s0 += (va.x + va.y) + (va.z + va.w);
        s1 += (vb.x + vb.y) + (vb.z + vb.w);
    }
    float s = s0 + s1;
    #pragma unroll
    for (int o = 16; o; o >>= 1) s += __shfl_down_sync(0xffffffffu, s, o);
    __shared__ float ss[8];
    if ((threadIdx.x & 31) == 0) ss[threadIdx.x >> 5] = s;
    __syncthreads();
    if (threadIdx.x < 8) {
        s = ss[threadIdx.x];
        #pragma unroll
        for (int o = 4; o; o >>= 1) s += __shfl_down_sync(0xffu, s, o);
        if (threadIdx.x == 0) g_part[b * RBLKS + blk] = s;
    }
}

// ---- transform role: one float4 per thread in each of 3 planes ----
__device__ __forceinline__ void transform_role(
    const float* __restrict__ imgs,
    const float* __restrict__ br,  const float* __restrict__ sat,
    const float* __restrict__ con, const int* __restrict__ tx,
    const int* __restrict__ ty,    const int* __restrict__ cx,
    const int* __restrict__ cy,    float* __restrict__ out,
    int b, int blk)
{
    int idx4 = blk * 256 + threadIdx.x;               // float4 index in plane
    int h    = idx4 >> 6;
    int w0   = (idx4 & 63) << 2;

    // One warp sums this image's 32 partials (L2-broadcast hits).
    __shared__ float sM0;
    if (threadIdx.x < 32) {
        float s = g_part[b * RBLKS + threadIdx.x];
        #pragma unroll
        for (int o = 16; o; o >>= 1) s += __shfl_down_sync(0xffffffffu, s, o);
        if (threadIdx.x == 0) sM0 = s * (1.0f / (float)CHW);
    }
    __syncthreads();

    // out = Af*v + Bf*channel_mean + Cf on valid pixels, else 0
    float a  = sat[b] * 2.0f;
    float k  = con[b] + 0.5f;
    float Af = k * a;
    float Bf = k * (1.0f - a);
    float Cf = (1.0f - k) * sM0 + (br[b] - 0.5f);

    int txs = tx[b] - SHIFT;
    int tys = ty[b] - SHIFT;
    int cxv = cx[b], cyv = cy[b];
    int xlo = max(0, cxv - 64), xhi = min(HH - 1, cxv + 63);
    int ylo = max(0, cyv - 64), yhi = min(WW - 1, cyv + 63);

    int  sh       = h + txs;
    bool rowvalid = (sh >= 0) & (sh < HH);
    bool rowcut   = (h >= xlo) & (h <= xhi);
    int  sh_c     = min(max(sh, 0), HH - 1);

    const float* src = imgs + (size_t)b * CHW + (size_t)sh_c * WW;

    float o0[4], o1[4], o2[4];
    #pragma unroll
    for (int j = 0; j < 4; j++) {
        int  w  = w0 + j;
        int  sw = w + tys;
        bool valid = rowvalid & (sw >= 0) & (sw < WW)
                   & !(rowcut & (w >= ylo) & (w <= yhi));
        int sw_c = min(max(sw, 0), WW - 1);
        if (valid) {
            float v0 = __ldcs(src + sw_c);            // last-use reads
            float v1 = __ldcs(src + HW + sw_c);
            float v2 = __ldcs(src + 2 * HW + sw_c);
            float m  = (v0 + v1 + v2) * (1.0f / 3.0f);
            float bm = fmaf(Bf, m, Cf);
            o0[j] = fmaf(Af, v0, bm);
            o1[j] = fmaf(Af, v1, bm);
            o2[j] = fmaf(Af, v2, bm);
        } else {
            o0[j] = 0.f; o1[j] = 0.f; o2[j] = 0.f;
        }
    }

    float* dst = out + (size_t)b * CHW + (size_t)h * WW + w0;
    __stcs((float4*)(dst),          make_float4(o0[0], o0[1], o0[2], o0[3]));
    __stcs((float4*)(dst + HW),     make_float4(o1[0], o1[1], o1[2], o1[3]));
    __stcs((float4*)(dst + 2 * HW), make_float4(o2[0], o2[1], o2[2], o2[3]));
}

// Mixed kernel. When mixed==1 (K1: 6144 blocks, 2048 reduce + 4096 transform),
// roles are INTERLEAVED by blockIdx.x % 3 so every dispatch wave carries both
// the DRAM-read stream (reduce half-1) and the DRAM-write stream (transform
// half-0) — the memory controller sees mixed traffic for the whole kernel.
// Otherwise: pure reduce (ntr==0) or pure transform (nred==0) endcaps.
__global__ void __launch_bounds__(256) fused_kernel(
    const float* __restrict__ imgs,
    const float* __restrict__ br,  const float* __restrict__ sat,
    const float* __restrict__ con, const int* __restrict__ tx,
    const int* __restrict__ ty,    const int* __restrict__ cx,
    const int* __restrict__ cy,    float* __restrict__ out,
    int tbase, int rbase, int nred, int ntr)
{
    if (nred > 0 && ntr > 0) {
        // interleaved: ratio 1 reduce : 2 transform (2048 : 4096)
        int r   = blockIdx.x / 3;
        int rem = blockIdx.x % 3;
        if (rem == 0) {
            reduce_role(imgs, rbase + r / RBLKS, r % RBLKS);
        } else {
            int tix = r * 2 + (rem - 1);
            transform_role(imgs, br, sat, con, tx, ty, cx, cy, out,
                           tbase + tix / BPI, tix % BPI);
        }
    } else if (nred > 0) {
        reduce_role(imgs, rbase + blockIdx.x / RBLKS, blockIdx.x % RBLKS);
    } else {
        transform_role(imgs, br, sat, con, tx, ty, cx, cy, out,
                       tbase + blockIdx.x / BPI, blockIdx.x % BPI);
    }
}

extern "C" void kernel_launch(void* const* d_in, const int* in_sizes, int n_in,
                              void* d_out, int out_size)
{
    const float* imgs = (const float*)d_in[0];
    const float* br   = (const float*)d_in[1];
    const float* sat  = (const float*)d_in[2];
    const float* con  = (const float*)d_in[3];
    const int*   tx   = (const int*)d_in[4];
    const int*   ty   = (const int*)d_in[5];
    const int*   cx   = (const int*)d_in[6];
    const int*   cy   = (const int*)d_in[7];
    float*       out  = (float*)d_out;

    const int RB = HALF * RBLKS;   // 2048 reduce blocks per half
    const int TB = HALF * BPI;     // 4096 transform blocks per half

    // K0: reduce half 0
    fused_kernel<<<RB, 256>>>(imgs, br, sat, con, tx, ty, cx, cy, out,
                              /*tbase*/0, /*rbase*/0, /*nred*/HALF, /*ntr*/0);
    // K1: reduce half 1 + transform half 0, roles interleaved mod 3
    fused_kernel<<<RB + TB, 256>>>(imgs, br, sat, con, tx, ty, cx, cy, out,
                              /*tbase*/0, /*rbase*/HALF, /*nred*/HALF, /*ntr*/HALF);
    // K2: transform half 1
    fused_kernel<<<TB, 256>>>(imgs, br, sat, con, tx, ty, cx, cy, out,
                              /*tbase*/HALF, /*rbase*/0, /*nred*/0, /*ntr*/HALF);
}